// round 16
// baseline (speedup 1.0000x reference)
#include <cuda_runtime.h>
#include <cuda_fp16.h>
#include <math.h>
#include <stdint.h>

#define NH 8
#define HD 64
#define DV 128
#define T_LEN 2048
#define S_LEN 2048
#define BM 64
#define BN 64
#define NIT (S_LEN / BN)
#define LAMBDA_INIT 0.7008206670670481f
#define ONE_MINUS_LI 0.2991793329329519f
#define QSCALE 0.18033688011112043f   /* 0.125 * log2(e) */

// ---- fp16 scratch ----
// Q: row-major halves. K/V: tile-contiguous, SW128-swizzled (see conv_kernel).
#define NQK (2 * 2 * NH * T_LEN * HD)     /* 4,194,304 */
#define NV  (2 * NH * S_LEN * DV)         /* 4,194,304 */
__device__ __half g_Qh[NQK];
__device__ __half g_Kh[NQK];   /* [bh2 0..31][kt 0..31][4096 halves: r*64 + ((c16^(r&7))<<3)+d7] */
__device__ __half g_Vh[NV];    /* [bh 0..15][kt 0..31][8192 halves: panel*4096 + r*64 + ...]    */
__device__ float g_lam_full;

// ---- smem layout ----
#define KOFF 0                   /* 6 K tiles (stream*3+buf) x 8192B */
#define VOFF 49152               /* 3 V tiles x 16384B               */
#define LOFF 98304               /* lrow[2][64] f32                  */
#define MBOFF 98816              /* 3 full mbarriers x 8B            */
#define EMOFF 98840              /* 3 empty mbarriers x 8B           */
#define SM_TOTAL 98944           /* x2 CTAs = 197888 <= 228KB SM     */
/* epilogue Obuf (64 x 132 f32 = 33792B) aliases the dead K ring at offset 0 */

__global__ void lam_kernel(const float* __restrict__ lq1, const float* __restrict__ lk1,
                           const float* __restrict__ lq2, const float* __restrict__ lk2) {
    int t = threadIdx.x;
    float d1 = lq1[t] * lk1[t] + lq1[t + 32] * lk1[t + 32];
    float d2 = lq2[t] * lk2[t] + lq2[t + 32] * lk2[t + 32];
#pragma unroll
    for (int o = 16; o > 0; o >>= 1) {
        d1 += __shfl_xor_sync(0xffffffffu, d1, o);
        d2 += __shfl_xor_sync(0xffffffffu, d2, o);
    }
    if (t == 0) g_lam_full = expf(d1) - expf(d2) + LAMBDA_INIT;
}

#define NQ4 (NQK / 4)          /* 1,048,576 Q float4 groups   */
#define NKG (NQK / 8)          /* 524,288 K 16B granules      */
#define NVG (NV / 8)           /* 524,288 V 16B granules      */

__device__ __forceinline__ uint4 pack8h(float4 a, float4 b) {
    uint4 r;
    asm("cvt.rn.f16x2.f32 %0, %2, %1;" : "=r"(r.x) : "f"(a.x), "f"(a.y));
    asm("cvt.rn.f16x2.f32 %0, %2, %1;" : "=r"(r.y) : "f"(a.z), "f"(a.w));
    asm("cvt.rn.f16x2.f32 %0, %2, %1;" : "=r"(r.z) : "f"(b.x), "f"(b.y));
    asm("cvt.rn.f16x2.f32 %0, %2, %1;" : "=r"(r.w) : "f"(b.z), "f"(b.w));
    return r;
}

__global__ void conv_kernel(const float* __restrict__ Q, const float* __restrict__ K,
                            const float* __restrict__ V) {
    int i = blockIdx.x * 256 + threadIdx.x;
    if (i < NQ4) {
        float4 v = ((const float4*)Q)[i];
        ((__half2*)g_Qh)[2 * i]     = __floats2half2_rn(v.x * QSCALE, v.y * QSCALE);
        ((__half2*)g_Qh)[2 * i + 1] = __floats2half2_rn(v.z * QSCALE, v.w * QSCALE);
    } else if (i < NQ4 + NKG) {
        int g = i - NQ4;
        int t = g >> 9;                 // tile = bh2*32 + kt
        int w = g & 511;
        int r = w >> 3, c16 = w & 7;
        const float* src = K + (((size_t)(t >> 5) * S_LEN) + (t & 31) * BN + r) * HD + c16 * 8;
        uint4 p = pack8h(*(const float4*)src, *(const float4*)(src + 4));
        size_t dst = (size_t)t * 4096 + r * 64 + ((c16 ^ (r & 7)) << 3);
        *(uint4*)(g_Kh + dst) = p;
    } else {
        int g = i - NQ4 - NKG;
        int t = g >> 10;                // tile = bh*32 + kt
        int w = g & 1023;
        int pn = w >> 9, w2 = w & 511;
        int r = w2 >> 3, c16 = w2 & 7;
        const float* src = V + (((size_t)(t >> 5) * S_LEN) + (t & 31) * BN + r) * DV + pn * 64 + c16 * 8;
        uint4 p = pack8h(*(const float4*)src, *(const float4*)(src + 4));
        size_t dst = (size_t)t * 8192 + pn * 4096 + r * 64 + ((c16 ^ (r & 7)) << 3);
        *(uint4*)(g_Vh + dst) = p;
    }
}

// ------------- asm helpers (plain-sm_103 legal) -------------
__device__ __forceinline__ uint32_t smem_u32(const void* p) {
    uint32_t a;
    asm("{ .reg .u64 t; cvta.to.shared.u64 t, %1; cvt.u32.u64 %0, t; }" : "=r"(a) : "l"(p));
    return a;
}
#define LDSM_X4(R, addr) \
    asm volatile("ldmatrix.sync.aligned.m8n8.x4.shared.b16 {%0,%1,%2,%3}, [%4];" \
        : "=r"((R)[0]), "=r"((R)[1]), "=r"((R)[2]), "=r"((R)[3]) : "r"(addr))
#define LDSM_X4T(R, addr) \
    asm volatile("ldmatrix.sync.aligned.m8n8.x4.trans.shared.b16 {%0,%1,%2,%3}, [%4];" \
        : "=r"((R)[0]), "=r"((R)[1]), "=r"((R)[2]), "=r"((R)[3]) : "r"(addr))
#define HMMA(C, A, b0, b1) \
    asm volatile("mma.sync.aligned.m16n8k16.row.col.f32.f16.f16.f32 " \
        "{%0,%1,%2,%3},{%4,%5,%6,%7},{%8,%9},{%0,%1,%2,%3};" \
        : "+f"((C)[0]), "+f"((C)[1]), "+f"((C)[2]), "+f"((C)[3]) \
        : "r"((A)[0]), "r"((A)[1]), "r"((A)[2]), "r"((A)[3]), "r"(b0), "r"(b1))

#define MBAR_INIT(mb, n) \
    asm volatile("mbarrier.init.shared.b64 [%0], %1;" :: "r"(mb), "r"((uint32_t)(n)) : "memory")
#define MBAR_EXPECT_TX(mb, n) \
    asm volatile("mbarrier.arrive.expect_tx.shared.b64 _, [%0], %1;" :: "r"(mb), "r"((uint32_t)(n)) : "memory")
#define MBAR_ARRIVE(mb) \
    asm volatile("mbarrier.arrive.shared.b64 _, [%0];" :: "r"(mb) : "memory")
#define BULK_G2S(dst, src, sz, mb) \
    asm volatile("cp.async.bulk.shared::cluster.global.mbarrier::complete_tx::bytes [%0], [%1], %2, [%3];" \
        :: "r"(dst), "l"(src), "r"((uint32_t)(sz)), "r"(mb) : "memory")

__device__ __forceinline__ void mbar_wait(uint32_t mb, uint32_t parity) {
    asm volatile(
        "{\n\t.reg .pred P1;\n\t"
        "WAIT_%=:\n\t"
        "mbarrier.try_wait.parity.acquire.cta.shared::cta.b64 P1, [%0], %1, 0x989680;\n\t"
        "@P1 bra.uni DONE_%=;\n\t"
        "bra.uni WAIT_%=;\n\t"
        "DONE_%=:\n\t}"
        :: "r"(mb), "r"(parity) : "memory");
}

__device__ __forceinline__ float ex2f(float x) {
    float r;
    asm("ex2.approx.f32 %0, %1;" : "=f"(r) : "f"(x));
    return r;
}
__device__ __forceinline__ uint32_t packh2(float lo, float hi) {
    uint32_t r;
    asm("cvt.rn.f16x2.f32 %0, %1, %2;" : "=r"(r) : "f"(hi), "f"(lo));
    return r;
}

__global__ __launch_bounds__(256, 2)
void diffattn_hmma_kernel(const float* __restrict__ subln, float* __restrict__ out)
{
    extern __shared__ char smem[];
    const uint32_t sb = smem_u32(smem);
    const int tid = threadIdx.x;
    const int wid = tid >> 5;
    const int lane = tid & 31;
    const int rg = wid >> 1;          // row group 0..3 -> rows rg*16..+15
    const int role = wid & 1;         // stream index (kept end-to-end)
    const int m0 = rg * 16;
    const int t0 = blockIdx.x * BM;
    const int b = blockIdx.y / NH;
    const int h = blockIdx.y % NH;

    const int lr = lane & 7, grp = lane >> 3;
    const int r0l = lane >> 2;            // 0..7
    const int cql = (lane & 3) * 2;

    // swizzled-lane components
    const int kr = ((grp & 2) << 2) + lr;           // K row within 16-row band (kr&7 == lr)
    const int kcol0 = (grp & 1);                     // 16B-chunk base for QK B-frag
    const int vrow0 = ((grp & 1) << 3) + lr;         // V row within 16-row k-band
    const int vcol0 = ((grp & 2) >> 1);              // 16B-chunk base for PV B-frag

    // mbarriers: full (tx-based, producer->consumer) and empty (8 warp arrives)
    if (tid == 0) {
        MBAR_INIT(sb + MBOFF + 0, 1);
        MBAR_INIT(sb + MBOFF + 8, 1);
        MBAR_INIT(sb + MBOFF + 16, 1);
        MBAR_INIT(sb + EMOFF + 0, 8);
        MBAR_INIT(sb + EMOFF + 8, 8);
        MBAR_INIT(sb + EMOFF + 16, 8);
    }
    __syncthreads();

    // ---- Q fragments (own stream), direct from gmem fp16 ----
    const __half* qg = g_Qh + ((size_t)(b * 2 * NH + 2 * h + role) * T_LEN + (t0 + m0)) * HD;
    uint32_t qf[4][4];
#pragma unroll
    for (int kc = 0; kc < 4; ++kc) {
        qf[kc][0] = *(const uint32_t*)(qg + (r0l)     * HD + kc * 16 + cql);
        qf[kc][1] = *(const uint32_t*)(qg + (r0l + 8) * HD + kc * 16 + cql);
        qf[kc][2] = *(const uint32_t*)(qg + (r0l)     * HD + kc * 16 + 8 + cql);
        qf[kc][3] = *(const uint32_t*)(qg + (r0l + 8) * HD + kc * 16 + 8 + cql);
    }

    // gmem tile bases (tile-contiguous swizzled scratch)
    const __half* k1g = g_Kh + (size_t)((b * 2 * NH + 2 * h)     * 32) * 4096;
    const __half* k2g = g_Kh + (size_t)((b * 2 * NH + 2 * h + 1) * 32) * 4096;
    const __half* vg  = g_Vh + (size_t)((b * NH + h) * 32) * 8192;

    float o[16][4];
#pragma unroll
    for (int nt = 0; nt < 16; ++nt)
#pragma unroll
        for (int j = 0; j < 4; ++j) o[nt][j] = 0.f;
    float lA = 0.f, lB = 0.f;

    // prologue: prefetch stages 0 and 1
    if (tid == 0) {
#pragma unroll
        for (int st = 0; st < 2; ++st) {
            uint32_t mb = sb + MBOFF + st * 8;
            MBAR_EXPECT_TX(mb, 32768);
            BULK_G2S(sb + KOFF + (0 * 3 + st) * 8192, k1g + st * 4096, 8192, mb);
            BULK_G2S(sb + KOFF + (1 * 3 + st) * 8192, k2g + st * 4096, 8192, mb);
            BULK_G2S(sb + VOFF + st * 16384, vg + (size_t)st * 8192, 16384, mb);
        }
    }

    for (int kt = 0; kt < NIT; ++kt) {
        const int buf = kt % 3;
        mbar_wait(sb + MBOFF + buf * 8, (kt / 3) & 1);

        const uint32_t kTileU = sb + KOFF + (uint32_t)(role * 3 + buf) * 8192 + (uint32_t)kr * 128;
        const uint32_t vTileU = sb + VOFF + (uint32_t)buf * 16384 + (uint32_t)vrow0 * 128;

        // ---- fused per-chunk pipeline: QK(np) -> exp(np) -> PV(np) ----
#pragma unroll
        for (int np = 0; np < 4; ++np) {
            // QK chunk: 4 LDSM + 8 HMMA -> 16 scores
            float s0[4] = {0.f, 0.f, 0.f, 0.f}, s1[4] = {0.f, 0.f, 0.f, 0.f};
#pragma unroll
            for (int kc = 0; kc < 4; ++kc) {
                uint32_t kb[4];
                uint32_t cx = (uint32_t)(((kc * 2 + kcol0) ^ lr) << 4);
                LDSM_X4(kb, kTileU + (uint32_t)np * 2048 + cx);
                HMMA(s0, qf[kc], kb[0], kb[1]);
                HMMA(s1, qf[kc], kb[2], kb[3]);
            }
            // exp chunk: 8 MUFU + pack
            uint32_t a[4];
            {
                float p0 = ex2f(s0[0]), p1 = ex2f(s0[1]), p2 = ex2f(s0[2]), p3 = ex2f(s0[3]);
                lA += p0 + p1; lB += p2 + p3;
                a[0] = packh2(p0, p1);
                a[1] = packh2(p2, p3);
            }
            {
                float p0 = ex2f(s1[0]), p1 = ex2f(s1[1]), p2 = ex2f(s1[2]), p3 = ex2f(s1[3]);
                lA += p0 + p1; lB += p2 + p3;
                a[2] = packh2(p0, p1);
                a[3] = packh2(p2, p3);
            }
            // PV chunk: 8 LDSM_T + 16 HMMA over this 16-wide k-band
            const uint32_t rbase = (uint32_t)np * 2048;
#pragma unroll
            for (int nv = 0; nv < 8; ++nv) {
                uint32_t vb[4];
                uint32_t vaddr = vTileU + ((nv >= 4) ? 8192u : 0u) + rbase
                               + (uint32_t)((((nv & 3) * 2 + vcol0) ^ lr) << 4);
                LDSM_X4T(vb, vaddr);
                HMMA(o[2 * nv],     a, vb[0], vb[1]);
                HMMA(o[2 * nv + 1], a, vb[2], vb[3]);
            }
        }

        // per-warp release of this stage (no CTA-wide barrier)
        if (lane == 0) MBAR_ARRIVE(sb + EMOFF + buf * 8);

        // producer: refill stage kt+2 once all 8 warps released its previous use
        if (tid == 0 && kt + 2 < NIT) {
            const int nf = kt + 2;            // fill index
            const int nb = nf % 3;
            if (nf >= 3) mbar_wait(sb + EMOFF + nb * 8, ((nf / 3) - 1) & 1);
            uint32_t mb = sb + MBOFF + nb * 8;
            MBAR_EXPECT_TX(mb, 32768);
            BULK_G2S(sb + KOFF + (0 * 3 + nb) * 8192, k1g + (size_t)nf * 4096, 8192, mb);
            BULK_G2S(sb + KOFF + (1 * 3 + nb) * 8192, k2g + (size_t)nf * 4096, 8192, mb);
            BULK_G2S(sb + VOFF + nb * 16384, vg + (size_t)nf * 8192, 16384, mb);
        }
    }

    // ---- epilogue: single cross-stream exchange ----
    lA += __shfl_xor_sync(0xffffffffu, lA, 1);
    lA += __shfl_xor_sync(0xffffffffu, lA, 2);
    lB += __shfl_xor_sync(0xffffffffu, lB, 1);
    lB += __shfl_xor_sync(0xffffffffu, lB, 2);
    float* lrow = (float*)(smem + LOFF);
    if ((lane & 3) == 0) {
        lrow[role * 64 + m0 + r0l] = lA;
        lrow[role * 64 + m0 + 8 + r0l] = lB;
    }
    __syncthreads();   // all warps exited loop: lrow visible, K ring dead

    const float lam = g_lam_full;
    const int rA = m0 + r0l, rB = rA + 8;
    float* Obuf = (float*)smem;   // 64 x 132 f32, aliases dead K ring

    if (role == 1) {
        const float il2A = lam / lrow[64 + rA];
        const float il2B = lam / lrow[64 + rB];
#pragma unroll
        for (int nt = 0; nt < 16; ++nt) {
            int col = nt * 8 + cql;
            Obuf[rA * 132 + col]     = o[nt][0] * il2A;
            Obuf[rA * 132 + col + 1] = o[nt][1] * il2A;
            Obuf[rB * 132 + col]     = o[nt][2] * il2B;
            Obuf[rB * 132 + col + 1] = o[nt][3] * il2B;
        }
    }
    __syncthreads();

    if (role == 0) {
        const float il1A = 1.f / lrow[rA];
        const float il1B = 1.f / lrow[rB];
        float ssA = 0.f, ssB = 0.f;
#pragma unroll
        for (int nt = 0; nt < 16; ++nt) {
            int col = nt * 8 + cql;
            float d0 = o[nt][0] * il1A - Obuf[rA * 132 + col];
            float d1 = o[nt][1] * il1A - Obuf[rA * 132 + col + 1];
            float d2 = o[nt][2] * il1B - Obuf[rB * 132 + col];
            float d3 = o[nt][3] * il1B - Obuf[rB * 132 + col + 1];
            ssA += d0 * d0 + d1 * d1;
            ssB += d2 * d2 + d3 * d3;
            o[nt][0] = d0; o[nt][1] = d1; o[nt][2] = d2; o[nt][3] = d3;
        }
        ssA += __shfl_xor_sync(0xffffffffu, ssA, 1);
        ssA += __shfl_xor_sync(0xffffffffu, ssA, 2);
        ssB += __shfl_xor_sync(0xffffffffu, ssB, 1);
        ssB += __shfl_xor_sync(0xffffffffu, ssB, 2);
        const float nrmA = rsqrtf(ssA * (1.0f / 128.0f) + 1e-5f) * ONE_MINUS_LI;
        const float nrmB = rsqrtf(ssB * (1.0f / 128.0f) + 1e-5f) * ONE_MINUS_LI;

        float* opA = out + ((size_t)b * T_LEN + t0 + rA) * (NH * DV) + h * DV;
        float* opB = out + ((size_t)b * T_LEN + t0 + rB) * (NH * DV) + h * DV;
#pragma unroll
        for (int nt = 0; nt < 16; ++nt) {
            int col = nt * 8 + cql;
            float2 w = *(const float2*)(subln + col);
            *(float2*)(opA + col) = make_float2(o[nt][0] * nrmA * w.x, o[nt][1] * nrmA * w.y);
            *(float2*)(opB + col) = make_float2(o[nt][2] * nrmB * w.x, o[nt][3] * nrmB * w.y);
        }
    }
}

extern "C" void kernel_launch(void* const* d_in, const int* in_sizes, int n_in,
                              void* d_out, int out_size) {
    const float* queries = (const float*)d_in[0];
    const float* keys    = (const float*)d_in[1];
    const float* values  = (const float*)d_in[2];
    const float* lq1     = (const float*)d_in[3];
    const float* lk1     = (const float*)d_in[4];
    const float* lq2     = (const float*)d_in[5];
    const float* lk2     = (const float*)d_in[6];
    const float* subln   = (const float*)d_in[7];
    float* out = (float*)d_out;

    int B = in_sizes[0] / (2 * NH * T_LEN * HD);

    cudaFuncSetAttribute(diffattn_hmma_kernel,
                         cudaFuncAttributeMaxDynamicSharedMemorySize, SM_TOTAL);

    lam_kernel<<<1, 32>>>(lq1, lk1, lq2, lk2);
    int convThreads = NQ4 + NKG + NVG;
    conv_kernel<<<convThreads / 256, 256>>>(queries, keys, values);
    dim3 grid(T_LEN / BM, B * NH);
    diffattn_hmma_kernel<<<grid, 256, SM_TOTAL>>>(subln, out);
}

// round 17
// speedup vs baseline: 1.0542x; 1.0542x over previous
#include <cuda_runtime.h>
#include <cuda_fp16.h>
#include <math.h>
#include <stdint.h>

#define NH 8
#define HD 64
#define DV 128
#define T_LEN 2048
#define S_LEN 2048
#define BM 64
#define BN 64
#define NIT (S_LEN / BN)
#define LAMBDA_INIT 0.7008206670670481f
#define ONE_MINUS_LI 0.2991793329329519f
#define QSCALE 0.18033688011112043f   /* 0.125 * log2(e) */

// ---- fp16 scratch ----
// K/V: tile-contiguous, SW128-swizzled (see conv_kernel). Q converted in-kernel.
#define NQK (2 * 2 * NH * T_LEN * HD)     /* 4,194,304 */
#define NV  (2 * NH * S_LEN * DV)         /* 4,194,304 */
__device__ __half g_Kh[NQK];   /* [bh2 0..31][kt 0..31][4096 halves: r*64 + ((c16^(r&7))<<3)+d7] */
__device__ __half g_Vh[NV];    /* [bh 0..15][kt 0..31][8192 halves: panel*4096 + r*64 + ...]    */

// ---- smem layout ----
#define KOFF 0                   /* 6 K tiles (stream*3+buf) x 8192B */
#define VOFF 49152               /* 3 V tiles x 16384B               */
#define LOFF 98304               /* lrow[2][64] f32                  */
#define MBOFF 98816              /* 3 mbarriers x 8B                 */
#define SM_TOTAL 98944           /* x2 CTAs = 197888 <= 228KB SM     */
/* epilogue Obuf (64 x 132 f32 = 33792B) aliases the dead K ring at offset 0 */

#define NKG (NQK / 8)          /* 524,288 K 16B granules      */
#define NVG (NV / 8)           /* 524,288 V 16B granules      */

__device__ __forceinline__ uint4 pack8h(float4 a, float4 b) {
    uint4 r;
    asm("cvt.rn.f16x2.f32 %0, %2, %1;" : "=r"(r.x) : "f"(a.x), "f"(a.y));
    asm("cvt.rn.f16x2.f32 %0, %2, %1;" : "=r"(r.y) : "f"(a.z), "f"(a.w));
    asm("cvt.rn.f16x2.f32 %0, %2, %1;" : "=r"(r.z) : "f"(b.x), "f"(b.y));
    asm("cvt.rn.f16x2.f32 %0, %2, %1;" : "=r"(r.w) : "f"(b.z), "f"(b.w));
    return r;
}

__global__ void conv_kernel(const float* __restrict__ K, const float* __restrict__ V) {
    int i = blockIdx.x * 256 + threadIdx.x;
    if (i < NKG) {
        int g = i;
        int t = g >> 9;                 // tile = bh2*32 + kt
        int w = g & 511;
        int r = w >> 3, c16 = w & 7;
        const float* src = K + (((size_t)(t >> 5) * S_LEN) + (t & 31) * BN + r) * HD + c16 * 8;
        uint4 p = pack8h(*(const float4*)src, *(const float4*)(src + 4));
        size_t dst = (size_t)t * 4096 + r * 64 + ((c16 ^ (r & 7)) << 3);
        *(uint4*)(g_Kh + dst) = p;
    } else {
        int g = i - NKG;
        int t = g >> 10;                // tile = bh*32 + kt
        int w = g & 1023;
        int pn = w >> 9, w2 = w & 511;
        int r = w2 >> 3, c16 = w2 & 7;
        const float* src = V + (((size_t)(t >> 5) * S_LEN) + (t & 31) * BN + r) * DV + pn * 64 + c16 * 8;
        uint4 p = pack8h(*(const float4*)src, *(const float4*)(src + 4));
        size_t dst = (size_t)t * 8192 + pn * 4096 + r * 64 + ((c16 ^ (r & 7)) << 3);
        *(uint4*)(g_Vh + dst) = p;
    }
}

// ------------- asm helpers (plain-sm_103 legal) -------------
__device__ __forceinline__ uint32_t smem_u32(const void* p) {
    uint32_t a;
    asm("{ .reg .u64 t; cvta.to.shared.u64 t, %1; cvt.u32.u64 %0, t; }" : "=r"(a) : "l"(p));
    return a;
}
#define LDSM_X4(R, addr) \
    asm volatile("ldmatrix.sync.aligned.m8n8.x4.shared.b16 {%0,%1,%2,%3}, [%4];" \
        : "=r"((R)[0]), "=r"((R)[1]), "=r"((R)[2]), "=r"((R)[3]) : "r"(addr))
#define LDSM_X4T(R, addr) \
    asm volatile("ldmatrix.sync.aligned.m8n8.x4.trans.shared.b16 {%0,%1,%2,%3}, [%4];" \
        : "=r"((R)[0]), "=r"((R)[1]), "=r"((R)[2]), "=r"((R)[3]) : "r"(addr))
#define HMMA(C, A, b0, b1) \
    asm volatile("mma.sync.aligned.m16n8k16.row.col.f32.f16.f16.f32 " \
        "{%0,%1,%2,%3},{%4,%5,%6,%7},{%8,%9},{%0,%1,%2,%3};" \
        : "+f"((C)[0]), "+f"((C)[1]), "+f"((C)[2]), "+f"((C)[3]) \
        : "r"((A)[0]), "r"((A)[1]), "r"((A)[2]), "r"((A)[3]), "r"(b0), "r"(b1))

#define MBAR_INIT(mb, n) \
    asm volatile("mbarrier.init.shared.b64 [%0], %1;" :: "r"(mb), "r"((uint32_t)(n)) : "memory")
#define MBAR_EXPECT_TX(mb, n) \
    asm volatile("mbarrier.arrive.expect_tx.shared.b64 _, [%0], %1;" :: "r"(mb), "r"((uint32_t)(n)) : "memory")
#define BULK_G2S(dst, src, sz, mb) \
    asm volatile("cp.async.bulk.shared::cluster.global.mbarrier::complete_tx::bytes [%0], [%1], %2, [%3];" \
        :: "r"(dst), "l"(src), "r"((uint32_t)(sz)), "r"(mb) : "memory")

__device__ __forceinline__ void mbar_wait(uint32_t mb, uint32_t parity) {
    asm volatile(
        "{\n\t.reg .pred P1;\n\t"
        "WAIT_%=:\n\t"
        "mbarrier.try_wait.parity.acquire.cta.shared::cta.b64 P1, [%0], %1, 0x989680;\n\t"
        "@P1 bra.uni DONE_%=;\n\t"
        "bra.uni WAIT_%=;\n\t"
        "DONE_%=:\n\t}"
        :: "r"(mb), "r"(parity) : "memory");
}

__device__ __forceinline__ float ex2f(float x) {
    float r;
    asm("ex2.approx.f32 %0, %1;" : "=f"(r) : "f"(x));
    return r;
}
__device__ __forceinline__ uint32_t packh2(float lo, float hi) {
    uint32_t r;
    asm("cvt.rn.f16x2.f32 %0, %1, %2;" : "=r"(r) : "f"(hi), "f"(lo));
    return r;
}

__global__ __launch_bounds__(256, 2)
void diffattn_hmma_kernel(const float* __restrict__ Q,
                          const float* __restrict__ lq1, const float* __restrict__ lk1,
                          const float* __restrict__ lq2, const float* __restrict__ lk2,
                          const float* __restrict__ subln, float* __restrict__ out)
{
    extern __shared__ char smem[];
    const uint32_t sb = smem_u32(smem);
    const int tid = threadIdx.x;
    const int wid = tid >> 5;
    const int lane = tid & 31;
    const int rg = wid >> 1;          // row group 0..3 -> rows rg*16..+15
    const int role = wid & 1;         // stream index (kept end-to-end)
    const int m0 = rg * 16;
    const int t0 = blockIdx.x * BM;
    const int b = blockIdx.y / NH;
    const int h = blockIdx.y % NH;

    const int lr = lane & 7, grp = lane >> 3;
    const int r0l = lane >> 2;            // 0..7
    const int cql = (lane & 3) * 2;

    // swizzled-lane components
    const int kr = ((grp & 2) << 2) + lr;           // K row within 16-row band (kr&7 == lr)
    const int kcol0 = (grp & 1);                     // 16B-chunk base for QK B-frag
    const int vrow0 = ((grp & 1) << 3) + lr;         // V row within 16-row k-band
    const int vcol0 = ((grp & 2) >> 1);              // 16B-chunk base for PV B-frag

    // mbarriers
    if (tid == 0) {
        MBAR_INIT(sb + MBOFF + 0, 1);
        MBAR_INIT(sb + MBOFF + 8, 1);
        MBAR_INIT(sb + MBOFF + 16, 1);
    }
    __syncthreads();

    // ---- Q fragments: fp32 gmem -> scale -> fp16 in-register (no prepass) ----
    const float* qg = Q + ((size_t)(b * 2 * NH + 2 * h + role) * T_LEN + (t0 + m0)) * HD;
    uint32_t qf[4][4];
#pragma unroll
    for (int kc = 0; kc < 4; ++kc) {
        float2 v0 = *(const float2*)(qg + (r0l)     * HD + kc * 16 + cql);
        float2 v1 = *(const float2*)(qg + (r0l + 8) * HD + kc * 16 + cql);
        float2 v2 = *(const float2*)(qg + (r0l)     * HD + kc * 16 + 8 + cql);
        float2 v3 = *(const float2*)(qg + (r0l + 8) * HD + kc * 16 + 8 + cql);
        qf[kc][0] = packh2(v0.x * QSCALE, v0.y * QSCALE);
        qf[kc][1] = packh2(v1.x * QSCALE, v1.y * QSCALE);
        qf[kc][2] = packh2(v2.x * QSCALE, v2.y * QSCALE);
        qf[kc][3] = packh2(v3.x * QSCALE, v3.y * QSCALE);
    }

    // gmem tile bases (tile-contiguous swizzled scratch)
    const __half* k1g = g_Kh + (size_t)((b * 2 * NH + 2 * h)     * 32) * 4096;
    const __half* k2g = g_Kh + (size_t)((b * 2 * NH + 2 * h + 1) * 32) * 4096;
    const __half* vg  = g_Vh + (size_t)((b * NH + h) * 32) * 8192;

    float o[16][4];
#pragma unroll
    for (int nt = 0; nt < 16; ++nt)
#pragma unroll
        for (int j = 0; j < 4; ++j) o[nt][j] = 0.f;
    float lA = 0.f, lB = 0.f;

    // prologue: prefetch stages 0 and 1
    if (tid == 0) {
#pragma unroll
        for (int st = 0; st < 2; ++st) {
            uint32_t mb = sb + MBOFF + st * 8;
            MBAR_EXPECT_TX(mb, 32768);
            BULK_G2S(sb + KOFF + (0 * 3 + st) * 8192, k1g + st * 4096, 8192, mb);
            BULK_G2S(sb + KOFF + (1 * 3 + st) * 8192, k2g + st * 4096, 8192, mb);
            BULK_G2S(sb + VOFF + st * 16384, vg + (size_t)st * 8192, 16384, mb);
        }
    }

    for (int kt = 0; kt < NIT; ++kt) {
        const int buf = kt % 3;
        mbar_wait(sb + MBOFF + buf * 8, (kt / 3) & 1);

        const uint32_t kTileU = sb + KOFF + (uint32_t)(role * 3 + buf) * 8192 + (uint32_t)kr * 128;
        const uint32_t vTileU = sb + VOFF + (uint32_t)buf * 16384 + (uint32_t)vrow0 * 128;

        // ---- fused per-chunk pipeline: QK(np) -> exp(np) -> PV(np) ----
#pragma unroll
        for (int np = 0; np < 4; ++np) {
            // QK chunk: 4 LDSM + 8 HMMA -> 16 scores
            float s0[4] = {0.f, 0.f, 0.f, 0.f}, s1[4] = {0.f, 0.f, 0.f, 0.f};
#pragma unroll
            for (int kc = 0; kc < 4; ++kc) {
                uint32_t kb[4];
                uint32_t cx = (uint32_t)(((kc * 2 + kcol0) ^ lr) << 4);
                LDSM_X4(kb, kTileU + (uint32_t)np * 2048 + cx);
                HMMA(s0, qf[kc], kb[0], kb[1]);
                HMMA(s1, qf[kc], kb[2], kb[3]);
            }
            // exp chunk: 8 MUFU + pack
            uint32_t a[4];
            {
                float p0 = ex2f(s0[0]), p1 = ex2f(s0[1]), p2 = ex2f(s0[2]), p3 = ex2f(s0[3]);
                lA += p0 + p1; lB += p2 + p3;
                a[0] = packh2(p0, p1);
                a[1] = packh2(p2, p3);
            }
            {
                float p0 = ex2f(s1[0]), p1 = ex2f(s1[1]), p2 = ex2f(s1[2]), p3 = ex2f(s1[3]);
                lA += p0 + p1; lB += p2 + p3;
                a[2] = packh2(p0, p1);
                a[3] = packh2(p2, p3);
            }
            // PV chunk: 8 LDSM_T + 16 HMMA over this 16-wide k-band
            const uint32_t rbase = (uint32_t)np * 2048;
#pragma unroll
            for (int nv = 0; nv < 8; ++nv) {
                uint32_t vb[4];
                uint32_t vaddr = vTileU + ((nv >= 4) ? 8192u : 0u) + rbase
                               + (uint32_t)((((nv & 3) * 2 + vcol0) ^ lr) << 4);
                LDSM_X4T(vb, vaddr);
                HMMA(o[2 * nv],     a, vb[0], vb[1]);
                HMMA(o[2 * nv + 1], a, vb[2], vb[3]);
            }
        }

        __syncthreads();   // all warps done reading buf; safe to recycle
        if (kt + 2 < NIT && tid == 0) {
            const int nb = (kt + 2) % 3;
            uint32_t mb = sb + MBOFF + nb * 8;
            MBAR_EXPECT_TX(mb, 32768);
            BULK_G2S(sb + KOFF + (0 * 3 + nb) * 8192, k1g + (size_t)(kt + 2) * 4096, 8192, mb);
            BULK_G2S(sb + KOFF + (1 * 3 + nb) * 8192, k2g + (size_t)(kt + 2) * 4096, 8192, mb);
            BULK_G2S(sb + VOFF + nb * 16384, vg + (size_t)(kt + 2) * 8192, 16384, mb);
        }
    }

    // ---- epilogue: single cross-stream exchange ----
    lA += __shfl_xor_sync(0xffffffffu, lA, 1);
    lA += __shfl_xor_sync(0xffffffffu, lA, 2);
    lB += __shfl_xor_sync(0xffffffffu, lB, 1);
    lB += __shfl_xor_sync(0xffffffffu, lB, 2);
    float* lrow = (float*)(smem + LOFF);
    if ((lane & 3) == 0) {
        lrow[role * 64 + m0 + r0l] = lA;
        lrow[role * 64 + m0 + 8 + r0l] = lB;
    }
    __syncthreads();

    const int rA = m0 + r0l, rB = rA + 8;
    float* Obuf = (float*)smem;   // 64 x 132 f32, aliases dead K ring

    if (role == 1) {
        // compute lambda_full in-warp (no separate kernel launch)
        float d1 = lq1[lane] * lk1[lane] + lq1[lane + 32] * lk1[lane + 32];
        float d2 = lq2[lane] * lk2[lane] + lq2[lane + 32] * lk2[lane + 32];
#pragma unroll
        for (int sh = 16; sh > 0; sh >>= 1) {
            d1 += __shfl_xor_sync(0xffffffffu, d1, sh);
            d2 += __shfl_xor_sync(0xffffffffu, d2, sh);
        }
        const float lam = expf(d1) - expf(d2) + LAMBDA_INIT;
        const float il2A = lam / lrow[64 + rA];
        const float il2B = lam / lrow[64 + rB];
#pragma unroll
        for (int nt = 0; nt < 16; ++nt) {
            int col = nt * 8 + cql;
            Obuf[rA * 132 + col]     = o[nt][0] * il2A;
            Obuf[rA * 132 + col + 1] = o[nt][1] * il2A;
            Obuf[rB * 132 + col]     = o[nt][2] * il2B;
            Obuf[rB * 132 + col + 1] = o[nt][3] * il2B;
        }
    }
    __syncthreads();

    if (role == 0) {
        const float il1A = 1.f / lrow[rA];
        const float il1B = 1.f / lrow[rB];
        float ssA = 0.f, ssB = 0.f;
#pragma unroll
        for (int nt = 0; nt < 16; ++nt) {
            int col = nt * 8 + cql;
            float d0 = o[nt][0] * il1A - Obuf[rA * 132 + col];
            float d1 = o[nt][1] * il1A - Obuf[rA * 132 + col + 1];
            float d2 = o[nt][2] * il1B - Obuf[rB * 132 + col];
            float d3 = o[nt][3] * il1B - Obuf[rB * 132 + col + 1];
            ssA += d0 * d0 + d1 * d1;
            ssB += d2 * d2 + d3 * d3;
            o[nt][0] = d0; o[nt][1] = d1; o[nt][2] = d2; o[nt][3] = d3;
        }
        ssA += __shfl_xor_sync(0xffffffffu, ssA, 1);
        ssA += __shfl_xor_sync(0xffffffffu, ssA, 2);
        ssB += __shfl_xor_sync(0xffffffffu, ssB, 1);
        ssB += __shfl_xor_sync(0xffffffffu, ssB, 2);
        const float nrmA = rsqrtf(ssA * (1.0f / 128.0f) + 1e-5f) * ONE_MINUS_LI;
        const float nrmB = rsqrtf(ssB * (1.0f / 128.0f) + 1e-5f) * ONE_MINUS_LI;

        float* opA = out + ((size_t)b * T_LEN + t0 + rA) * (NH * DV) + h * DV;
        float* opB = out + ((size_t)b * T_LEN + t0 + rB) * (NH * DV) + h * DV;
#pragma unroll
        for (int nt = 0; nt < 16; ++nt) {
            int col = nt * 8 + cql;
            float2 w = *(const float2*)(subln + col);
            *(float2*)(opA + col) = make_float2(o[nt][0] * nrmA * w.x, o[nt][1] * nrmA * w.y);
            *(float2*)(opB + col) = make_float2(o[nt][2] * nrmB * w.x, o[nt][3] * nrmB * w.y);
        }
    }
}

extern "C" void kernel_launch(void* const* d_in, const int* in_sizes, int n_in,
                              void* d_out, int out_size) {
    const float* queries = (const float*)d_in[0];
    const float* keys    = (const float*)d_in[1];
    const float* values  = (const float*)d_in[2];
    const float* lq1     = (const float*)d_in[3];
    const float* lk1     = (const float*)d_in[4];
    const float* lq2     = (const float*)d_in[5];
    const float* lk2     = (const float*)d_in[6];
    const float* subln   = (const float*)d_in[7];
    float* out = (float*)d_out;

    int B = in_sizes[0] / (2 * NH * T_LEN * HD);

    cudaFuncSetAttribute(diffattn_hmma_kernel,
                         cudaFuncAttributeMaxDynamicSharedMemorySize, SM_TOTAL);

    int convThreads = NKG + NVG;
    conv_kernel<<<convThreads / 256, 256>>>(keys, values);
    dim3 grid(T_LEN / BM, B * NH);
    diffattn_hmma_kernel<<<grid, 256, SM_TOTAL>>>(queries, lq1, lk1, lq2, lk2, subln, out);
}